// round 10
// baseline (speedup 1.0000x reference)
#include <cuda_runtime.h>
#include <cuda_fp16.h>
#include <cstdint>

#define NPOS 8192
#define CH 64
#define BM 64          // q-rows per group (4 warps x 16); CTA covers 2*BM = 128 rows
#define BN 128         // keys per tile
#define NT (NPOS / BN) // 64
#define LOG2E 1.4426950408889634f

// ---------------- device scratch ----------------
#define TOT_ELEMS (2 * NPOS * CH)
__device__ __half g_hi[TOT_ELEMS];    // [b][n][c] fp16 hi
__device__ __half g_lo[TOT_ELEMS];    // [b][n][c] fp16 lo residual

// ---------------- helpers ----------------
__device__ __forceinline__ uint32_t smem_u32(const void* p) {
    uint32_t a;
    asm("{ .reg .u64 t; cvta.to.shared.u64 t, %1; cvt.u32.u64 %0, t; }" : "=r"(a) : "l"(p));
    return a;
}
__device__ __forceinline__ float ex2f(float v) {
    float r; asm("ex2.approx.ftz.f32 %0, %1;" : "=f"(r) : "f"(v)); return r;
}
__device__ __forceinline__ uint32_t h2u(__half2 h) { return *reinterpret_cast<uint32_t*>(&h); }

__device__ __forceinline__ void cp_async16(uint32_t dst, const void* src) {
    asm volatile("cp.async.cg.shared.global [%0], [%1], 16;" :: "r"(dst), "l"(src) : "memory");
}
__device__ __forceinline__ void cp_commit() {
    asm volatile("cp.async.commit_group;" ::: "memory");
}
template <int N>
__device__ __forceinline__ void cp_wait() {
    asm volatile("cp.async.wait_group %0;" :: "n"(N) : "memory");
}

__device__ __forceinline__ void ldsm_x4(uint32_t* r, uint32_t addr) {
    asm volatile("ldmatrix.sync.aligned.m8n8.x4.shared.b16 {%0,%1,%2,%3}, [%4];"
        : "=r"(r[0]), "=r"(r[1]), "=r"(r[2]), "=r"(r[3]) : "r"(addr));
}
__device__ __forceinline__ void ldsm_x4_trans(uint32_t* r, uint32_t addr) {
    asm volatile("ldmatrix.sync.aligned.m8n8.x4.trans.shared.b16 {%0,%1,%2,%3}, [%4];"
        : "=r"(r[0]), "=r"(r[1]), "=r"(r[2]), "=r"(r[3]) : "r"(addr));
}

// mma.sync m16n8k16 f16 -> f32 accumulate
__device__ __forceinline__ void mma16816(float* d, const uint32_t* a, const uint32_t* b) {
    asm volatile(
        "mma.sync.aligned.m16n8k16.row.col.f32.f16.f16.f32 "
        "{%0,%1,%2,%3}, {%4,%5,%6,%7}, {%8,%9}, {%0,%1,%2,%3};"
        : "+f"(d[0]), "+f"(d[1]), "+f"(d[2]), "+f"(d[3])
        : "r"(a[0]), "r"(a[1]), "r"(a[2]), "r"(a[3]), "r"(b[0]), "r"(b[1]));
}

// ---------------- smem layout ----------------
#define KSTR 72                         // row stride in halfs (64 + 8 pad)
#define KTILE (BN * KSTR * 2)           // one hi or lo tile = 18432 B
#define BUFSZ (2 * KTILE)               // hi + lo = 36864 B
#define SMEM_TOTAL (3 * BUFSZ)          // triple-buffered = 110592 B (1 CTA/SM)

// ---------------- pre-pass: fp32 -> fp16 hi/lo ----------------
__global__ __launch_bounds__(256) void convert_kernel(const float* __restrict__ x)
{
    size_t i4 = ((size_t)blockIdx.x * 256 + threadIdx.x) * 4;
    float4 v = *(const float4*)(x + i4);
    __half h0 = __float2half_rn(v.x), h1 = __float2half_rn(v.y);
    __half h2 = __float2half_rn(v.z), h3 = __float2half_rn(v.w);
    uint2 hw = make_uint2(h2u(__halves2half2(h0, h1)), h2u(__halves2half2(h2, h3)));
    *(uint2*)(g_hi + i4) = hw;
    __half l0 = __float2half_rn(v.x - __half2float(h0));
    __half l1 = __float2half_rn(v.y - __half2float(h1));
    __half l2 = __float2half_rn(v.z - __half2float(h2));
    __half l3 = __float2half_rn(v.w - __half2float(h3));
    uint2 lw = make_uint2(h2u(__halves2half2(l0, l1)), h2u(__halves2half2(l2, l3)));
    *(uint2*)(g_lo + i4) = lw;
}

// ---------------- main kernel: delayed-GEMM2 software pipeline ----------------
__global__ __launch_bounds__(256, 1) void attn_kernel(
    const float* __restrict__ x,
    const float* __restrict__ gamma_p,
    float* __restrict__ out)
{
    extern __shared__ __align__(128) char smem[];
    const uint32_t sb = smem_u32(smem);
    const int tid  = threadIdx.x;
    const int w    = tid >> 5;
    const int lane = tid & 31;
    const int q4   = lane >> 2;
    const int qm   = lane & 3;
    const int grp  = w >> 2;          // q-subtile within CTA
    const int wg   = w & 3;           // warp within group
    const int b    = blockIdx.y;
    const int i0   = blockIdx.x * (2 * BM) + grp * BM;

    const __half* xhi = g_hi + (size_t)b * NPOS * CH;
    const __half* xlo = g_lo + (size_t)b * NPOS * CH;

    // ---- prefetch one shared K tile (hi+lo), all 256 threads ----
    auto prefetch = [&](int jt, int buf) {
        const uint32_t d = sb + (uint32_t)buf * BUFSZ;
        const int j0 = jt * BN;
        #pragma unroll
        for (int it = 0; it < 4; ++it) {           // 128 rows x 8 chunks of 16B
            int lin = it * 256 + tid;
            int row = lin >> 3, c16 = (lin & 7) * 8;
            uint32_t so = (uint32_t)(row * KSTR + c16) * 2;
            const size_t go = (size_t)(j0 + row) * CH + c16;
            cp_async16(d + so, xhi + go);
            cp_async16(d + KTILE + so, xlo + go);
        }
        cp_commit();
    };

    prefetch(0, 0);

    // ---- Q fragments (hi only) ----
    uint32_t Qh[4][4];
    {
        const int r0 = i0 + wg * 16 + q4;
        #pragma unroll
        for (int kc = 0; kc < 4; ++kc) {
            int c = kc * 16 + qm * 2;
            Qh[kc][0] = *(const uint32_t*)(xhi + (size_t)r0 * CH + c);
            Qh[kc][1] = *(const uint32_t*)(xhi + (size_t)(r0 + 8) * CH + c);
            Qh[kc][2] = *(const uint32_t*)(xhi + (size_t)r0 * CH + c + 8);
            Qh[kc][3] = *(const uint32_t*)(xhi + (size_t)(r0 + 8) * CH + c + 8);
        }
    }

    // ldmatrix per-lane address offsets (within a tile)
    const uint32_t aoff1 = (uint32_t)((((lane >> 4) & 1) * 8 + (lane & 7)) * KSTR
                                      + ((lane >> 3) & 1) * 8) * 2;
    const uint32_t aoff2 = (uint32_t)(((( lane >> 3) & 1) * 8 + (lane & 7)) * KSTR
                                      + ((lane >> 4) & 1) * 8) * 2;

    float m0 = -1e30f, m1 = -1e30f, l0 = 0.0f, l1 = 0.0f;
    float O[8][4];
    #pragma unroll
    for (int nb = 0; nb < 8; ++nb)
        #pragma unroll
        for (int e = 0; e < 4; ++e) O[nb][e] = 0.0f;

    uint32_t Ph[8][4];   // P fragments of the PREVIOUS tile (consumed by delayed GEMM2)

    for (int jt = 0; jt < NT; ++jt) {
        cp_wait<0>();
        __syncthreads();
        if (jt + 1 < NT) prefetch(jt + 1, (jt + 1) % 3);

        const uint32_t kb = sb + (uint32_t)(jt % 3) * BUFSZ;

        // ---- GEMM1: S(16x128) = Qhi*Khi + Qhi*Klo ----
        float S[16][4];
        #pragma unroll
        for (int nb = 0; nb < 16; ++nb)
            #pragma unroll
            for (int e = 0; e < 4; ++e) S[nb][e] = 0.0f;

        #pragma unroll
        for (int kc = 0; kc < 4; ++kc) {
            #pragma unroll
            for (int jb = 0; jb < 8; ++jb) {
                uint32_t a = kb + aoff1 + (uint32_t)((jb * 16 * KSTR + kc * 16) * 2);
                uint32_t bh[4], bl[4];
                ldsm_x4(bh, a);
                ldsm_x4(bl, a + KTILE);
                mma16816(S[jb * 2],     Qh[kc], bh);
                mma16816(S[jb * 2],     Qh[kc], bl);
                mma16816(S[jb * 2 + 1], Qh[kc], bh + 2);
                mma16816(S[jb * 2 + 1], Qh[kc], bl + 2);
            }
        }

        // ---- delayed GEMM2: O += P(jt-1) * V(jt-1)  (tensor work overlapping softmax below) ----
        if (jt > 0) {
            const uint32_t kbp = sb + (uint32_t)((jt - 1) % 3) * BUFSZ;
            #pragma unroll
            for (int kk = 0; kk < 8; ++kk) {
                #pragma unroll
                for (int cb = 0; cb < 4; ++cb) {
                    uint32_t a = kbp + aoff2 + (uint32_t)((kk * 16 * KSTR + cb * 16) * 2);
                    uint32_t bh[4];
                    ldsm_x4_trans(bh, a);
                    mma16816(O[cb * 2],     Ph[kk], bh);
                    mma16816(O[cb * 2 + 1], Ph[kk], bh + 2);
                }
            }
        }

        // ---- online softmax for tile jt (MUFU/FMA; scheduler overlaps with GEMM2 above) ----
        float mx0 = -1e30f, mx1 = -1e30f;
        #pragma unroll
        for (int nb = 0; nb < 16; ++nb) {
            mx0 = fmaxf(mx0, fmaxf(S[nb][0], S[nb][1]));
            mx1 = fmaxf(mx1, fmaxf(S[nb][2], S[nb][3]));
        }
        mx0 = fmaxf(mx0, __shfl_xor_sync(0xffffffffu, mx0, 1));
        mx0 = fmaxf(mx0, __shfl_xor_sync(0xffffffffu, mx0, 2));
        mx1 = fmaxf(mx1, __shfl_xor_sync(0xffffffffu, mx1, 1));
        mx1 = fmaxf(mx1, __shfl_xor_sync(0xffffffffu, mx1, 2));
        float mn0 = fmaxf(m0, mx0), mn1 = fmaxf(m1, mx1);

        // rescale O only when the running max moved (rare: diagonal dominance).
        // NOTE: sits after the delayed GEMM2 in program order, so c applies to all j <= jt-1.
        if (mn0 > m0 || mn1 > m1) {
            float c0 = ex2f((m0 - mn0) * LOG2E), c1 = ex2f((m1 - mn1) * LOG2E);
            l0 *= c0; l1 *= c1;
            #pragma unroll
            for (int nb = 0; nb < 8; ++nb) {
                O[nb][0] *= c0; O[nb][1] *= c0; O[nb][2] *= c1; O[nb][3] *= c1;
            }
            m0 = mn0; m1 = mn1;
        }
        const float nmL0 = -m0 * LOG2E, nmL1 = -m1 * LOG2E;

        float s0 = 0.0f, s1 = 0.0f;
        #pragma unroll
        for (int kk = 0; kk < 8; ++kk) {
            #pragma unroll
            for (int t = 0; t < 2; ++t) {
                int nb = 2 * kk + t;
                float e0 = ex2f(fmaf(S[nb][0], LOG2E, nmL0));
                float e1 = ex2f(fmaf(S[nb][1], LOG2E, nmL0));
                float e2 = ex2f(fmaf(S[nb][2], LOG2E, nmL1));
                float e3 = ex2f(fmaf(S[nb][3], LOG2E, nmL1));
                s0 += e0 + e1; s1 += e2 + e3;
                Ph[kk][2 * t + 0] = h2u(__floats2half2_rn(e0, e1));
                Ph[kk][2 * t + 1] = h2u(__floats2half2_rn(e2, e3));
            }
        }
        s0 += __shfl_xor_sync(0xffffffffu, s0, 1);
        s0 += __shfl_xor_sync(0xffffffffu, s0, 2);
        s1 += __shfl_xor_sync(0xffffffffu, s1, 1);
        s1 += __shfl_xor_sync(0xffffffffu, s1, 2);
        l0 += s0;
        l1 += s1;
    }

    // ---- tail: GEMM2 for the final tile ----
    {
        const uint32_t kbp = sb + (uint32_t)((NT - 1) % 3) * BUFSZ;
        #pragma unroll
        for (int kk = 0; kk < 8; ++kk) {
            #pragma unroll
            for (int cb = 0; cb < 4; ++cb) {
                uint32_t a = kbp + aoff2 + (uint32_t)((kk * 16 * KSTR + cb * 16) * 2);
                uint32_t bh[4];
                ldsm_x4_trans(bh, a);
                mma16816(O[cb * 2],     Ph[kk], bh);
                mma16816(O[cb * 2 + 1], Ph[kk], bh + 2);
            }
        }
    }

    // ---- epilogue: out = gamma * (O / l) + x ----
    const float inv0 = 1.0f / l0, inv1 = 1.0f / l1;
    const float gm = __ldg(gamma_p);
    const float* xb = x   + (size_t)b * NPOS * CH;
    float*       ob = out + (size_t)b * NPOS * CH;
    const int gr0 = i0 + wg * 16 + q4;
    const int gr1 = gr0 + 8;
    #pragma unroll
    for (int nb = 0; nb < 8; ++nb) {
        int c = nb * 8 + qm * 2;
        float2 xv0 = *(const float2*)(xb + (size_t)gr0 * CH + c);
        float2 xv1 = *(const float2*)(xb + (size_t)gr1 * CH + c);
        float2 o0, o1;
        o0.x = fmaf(gm, O[nb][0] * inv0, xv0.x);
        o0.y = fmaf(gm, O[nb][1] * inv0, xv0.y);
        o1.x = fmaf(gm, O[nb][2] * inv1, xv1.x);
        o1.y = fmaf(gm, O[nb][3] * inv1, xv1.y);
        *(float2*)(ob + (size_t)gr0 * CH + c) = o0;
        *(float2*)(ob + (size_t)gr1 * CH + c) = o1;
    }
}

// ---------------- launch ----------------
extern "C" void kernel_launch(void* const* d_in, const int* in_sizes, int n_in,
                              void* d_out, int out_size)
{
    const float* x     = (const float*)d_in[0];
    const float* gamma = (const float*)d_in[1];
    float* out         = (float*)d_out;

    cudaFuncSetAttribute(attn_kernel,
                         cudaFuncAttributeMaxDynamicSharedMemorySize, SMEM_TOTAL);

    convert_kernel<<<TOT_ELEMS / (256 * 4), 256>>>(x);
    attn_kernel<<<dim3(NPOS / (2 * BM), 2), 256, SMEM_TOTAL>>>(x, gamma, out);
}

// round 11
// speedup vs baseline: 1.1267x; 1.1267x over previous
#include <cuda_runtime.h>
#include <cuda_fp16.h>
#include <cstdint>

#define NPOS 8192
#define CH 64
#define BM 64          // q-rows per group (4 warps x 16); CTA covers 2*BM = 128 rows
#define BN 128         // keys per tile
#define NT (NPOS / BN) // 64
#define LOG2E 1.4426950408889634f

// ---------------- device scratch ----------------
#define TOT_ELEMS (2 * NPOS * CH)
__device__ __half g_hi[TOT_ELEMS];    // [b][n][c] fp16 hi
__device__ __half g_lo[TOT_ELEMS];    // [b][n][c] fp16 lo residual

// ---------------- helpers ----------------
__device__ __forceinline__ uint32_t smem_u32(const void* p) {
    uint32_t a;
    asm("{ .reg .u64 t; cvta.to.shared.u64 t, %1; cvt.u32.u64 %0, t; }" : "=r"(a) : "l"(p));
    return a;
}
__device__ __forceinline__ float ex2f(float v) {
    float r; asm("ex2.approx.ftz.f32 %0, %1;" : "=f"(r) : "f"(v)); return r;
}
__device__ __forceinline__ uint32_t h2u(__half2 h) { return *reinterpret_cast<uint32_t*>(&h); }

__device__ __forceinline__ void cp_async16(uint32_t dst, const void* src) {
    asm volatile("cp.async.cg.shared.global [%0], [%1], 16;" :: "r"(dst), "l"(src) : "memory");
}
__device__ __forceinline__ void cp_commit() {
    asm volatile("cp.async.commit_group;" ::: "memory");
}
template <int N>
__device__ __forceinline__ void cp_wait() {
    asm volatile("cp.async.wait_group %0;" :: "n"(N) : "memory");
}

__device__ __forceinline__ void ldsm_x4(uint32_t* r, uint32_t addr) {
    asm volatile("ldmatrix.sync.aligned.m8n8.x4.shared.b16 {%0,%1,%2,%3}, [%4];"
        : "=r"(r[0]), "=r"(r[1]), "=r"(r[2]), "=r"(r[3]) : "r"(addr));
}
__device__ __forceinline__ void ldsm_x4_trans(uint32_t* r, uint32_t addr) {
    asm volatile("ldmatrix.sync.aligned.m8n8.x4.trans.shared.b16 {%0,%1,%2,%3}, [%4];"
        : "=r"(r[0]), "=r"(r[1]), "=r"(r[2]), "=r"(r[3]) : "r"(addr));
}

// mma.sync m16n8k16 f16 -> f32 accumulate
__device__ __forceinline__ void mma16816(float* d, const uint32_t* a, const uint32_t* b) {
    asm volatile(
        "mma.sync.aligned.m16n8k16.row.col.f32.f16.f16.f32 "
        "{%0,%1,%2,%3}, {%4,%5,%6,%7}, {%8,%9}, {%0,%1,%2,%3};"
        : "+f"(d[0]), "+f"(d[1]), "+f"(d[2]), "+f"(d[3])
        : "r"(a[0]), "r"(a[1]), "r"(a[2]), "r"(a[3]), "r"(b[0]), "r"(b[1]));
}

// ---------------- smem layout ----------------
#define KSTR 72                         // row stride in halfs (64 + 8 pad)
#define KTILE (BN * KSTR * 2)           // one hi or lo tile = 18432 B
#define BUFSZ (2 * KTILE)               // hi + lo = 36864 B
#define SMEM_TOTAL (3 * BUFSZ)          // triple-buffered = 110592 B (1 CTA/SM)

// ---------------- pre-pass: fp32 -> fp16 hi/lo ----------------
__global__ __launch_bounds__(256) void convert_kernel(const float* __restrict__ x)
{
    size_t i4 = ((size_t)blockIdx.x * 256 + threadIdx.x) * 4;
    float4 v = *(const float4*)(x + i4);
    __half h0 = __float2half_rn(v.x), h1 = __float2half_rn(v.y);
    __half h2 = __float2half_rn(v.z), h3 = __float2half_rn(v.w);
    uint2 hw = make_uint2(h2u(__halves2half2(h0, h1)), h2u(__halves2half2(h2, h3)));
    *(uint2*)(g_hi + i4) = hw;
    __half l0 = __float2half_rn(v.x - __half2float(h0));
    __half l1 = __float2half_rn(v.y - __half2float(h1));
    __half l2 = __float2half_rn(v.z - __half2float(h2));
    __half l3 = __float2half_rn(v.w - __half2float(h3));
    uint2 lw = make_uint2(h2u(__halves2half2(l0, l1)), h2u(__halves2half2(l2, l3)));
    *(uint2*)(g_lo + i4) = lw;
}

// ---------------- main kernel: fused exp->GEMM2 per k-block ----------------
__global__ __launch_bounds__(256, 1) void attn_kernel(
    const float* __restrict__ x,
    const float* __restrict__ gamma_p,
    float* __restrict__ out)
{
    extern __shared__ __align__(128) char smem[];
    const uint32_t sb = smem_u32(smem);
    const int tid  = threadIdx.x;
    const int w    = tid >> 5;
    const int lane = tid & 31;
    const int q4   = lane >> 2;
    const int qm   = lane & 3;
    const int grp  = w >> 2;          // q-subtile within CTA
    const int wg   = w & 3;           // warp within group
    const int b    = blockIdx.y;
    const int i0   = blockIdx.x * (2 * BM) + grp * BM;

    const __half* xhi = g_hi + (size_t)b * NPOS * CH;
    const __half* xlo = g_lo + (size_t)b * NPOS * CH;

    // ---- prefetch one shared K tile (hi+lo), all 256 threads ----
    auto prefetch = [&](int jt, int buf) {
        const uint32_t d = sb + (uint32_t)buf * BUFSZ;
        const int j0 = jt * BN;
        #pragma unroll
        for (int it = 0; it < 4; ++it) {           // 128 rows x 8 chunks of 16B
            int lin = it * 256 + tid;
            int row = lin >> 3, c16 = (lin & 7) * 8;
            uint32_t so = (uint32_t)(row * KSTR + c16) * 2;
            const size_t go = (size_t)(j0 + row) * CH + c16;
            cp_async16(d + so, xhi + go);
            cp_async16(d + KTILE + so, xlo + go);
        }
        cp_commit();
    };

    prefetch(0, 0);

    // ---- Q fragments (hi only) ----
    uint32_t Qh[4][4];
    {
        const int r0 = i0 + wg * 16 + q4;
        #pragma unroll
        for (int kc = 0; kc < 4; ++kc) {
            int c = kc * 16 + qm * 2;
            Qh[kc][0] = *(const uint32_t*)(xhi + (size_t)r0 * CH + c);
            Qh[kc][1] = *(const uint32_t*)(xhi + (size_t)(r0 + 8) * CH + c);
            Qh[kc][2] = *(const uint32_t*)(xhi + (size_t)r0 * CH + c + 8);
            Qh[kc][3] = *(const uint32_t*)(xhi + (size_t)(r0 + 8) * CH + c + 8);
        }
    }

    // ldmatrix per-lane address offsets (within a tile)
    const uint32_t aoff1 = (uint32_t)((((lane >> 4) & 1) * 8 + (lane & 7)) * KSTR
                                      + ((lane >> 3) & 1) * 8) * 2;
    const uint32_t aoff2 = (uint32_t)(((( lane >> 3) & 1) * 8 + (lane & 7)) * KSTR
                                      + ((lane >> 4) & 1) * 8) * 2;

    float m0 = -1e30f, m1 = -1e30f;
    float l0 = 0.0f, l1 = 0.0f;      // PER-THREAD partial sums; reduced once at the end
    float O[8][4];
    #pragma unroll
    for (int nb = 0; nb < 8; ++nb)
        #pragma unroll
        for (int e = 0; e < 4; ++e) O[nb][e] = 0.0f;

    for (int jt = 0; jt < NT; ++jt) {
        if (jt + 1 < NT) { prefetch(jt + 1, (jt + 1) % 3); cp_wait<1>(); }
        else             { cp_wait<0>(); }
        __syncthreads();

        const uint32_t kb = sb + (uint32_t)(jt % 3) * BUFSZ;

        // ---- GEMM1: S(16x128) = Qhi*Khi + Qhi*Klo ----
        float S[16][4];
        #pragma unroll
        for (int nb = 0; nb < 16; ++nb)
            #pragma unroll
            for (int e = 0; e < 4; ++e) S[nb][e] = 0.0f;

        #pragma unroll
        for (int kc = 0; kc < 4; ++kc) {
            #pragma unroll
            for (int jb = 0; jb < 8; ++jb) {
                uint32_t a = kb + aoff1 + (uint32_t)((jb * 16 * KSTR + kc * 16) * 2);
                uint32_t bh[4], bl[4];
                ldsm_x4(bh, a);
                ldsm_x4(bl, a + KTILE);
                mma16816(S[jb * 2],     Qh[kc], bh);
                mma16816(S[jb * 2],     Qh[kc], bl);
                mma16816(S[jb * 2 + 1], Qh[kc], bh + 2);
                mma16816(S[jb * 2 + 1], Qh[kc], bl + 2);
            }
        }

        // ---- row max + rare O-rescale ----
        float mx0 = -1e30f, mx1 = -1e30f;
        #pragma unroll
        for (int nb = 0; nb < 16; ++nb) {
            mx0 = fmaxf(mx0, fmaxf(S[nb][0], S[nb][1]));
            mx1 = fmaxf(mx1, fmaxf(S[nb][2], S[nb][3]));
        }
        mx0 = fmaxf(mx0, __shfl_xor_sync(0xffffffffu, mx0, 1));
        mx0 = fmaxf(mx0, __shfl_xor_sync(0xffffffffu, mx0, 2));
        mx1 = fmaxf(mx1, __shfl_xor_sync(0xffffffffu, mx1, 1));
        mx1 = fmaxf(mx1, __shfl_xor_sync(0xffffffffu, mx1, 2));
        float mn0 = fmaxf(m0, mx0), mn1 = fmaxf(m1, mx1);

        if (mn0 > m0 || mn1 > m1) {
            float c0 = ex2f((m0 - mn0) * LOG2E), c1 = ex2f((m1 - mn1) * LOG2E);
            l0 *= c0; l1 *= c1;     // per-thread partials scale uniformly
            #pragma unroll
            for (int nb = 0; nb < 8; ++nb) {
                O[nb][0] *= c0; O[nb][1] *= c0; O[nb][2] *= c1; O[nb][3] *= c1;
            }
            m0 = mn0; m1 = mn1;
        }
        const float nmL0 = -m0 * LOG2E, nmL1 = -m1 * LOG2E;

        // ---- fused: exp/pack for k-block kk, then its GEMM2 MMAs immediately ----
        // exp(kk+1) is independent of MMA(kk) -> MUFU overlaps the tensor pipe.
        #pragma unroll
        for (int kk = 0; kk < 8; ++kk) {
            uint32_t Ph[4];
            #pragma unroll
            for (int t = 0; t < 2; ++t) {
                int nb = 2 * kk + t;
                float e0 = ex2f(fmaf(S[nb][0], LOG2E, nmL0));
                float e1 = ex2f(fmaf(S[nb][1], LOG2E, nmL0));
                float e2 = ex2f(fmaf(S[nb][2], LOG2E, nmL1));
                float e3 = ex2f(fmaf(S[nb][3], LOG2E, nmL1));
                l0 += e0 + e1; l1 += e2 + e3;
                Ph[2 * t + 0] = h2u(__floats2half2_rn(e0, e1));
                Ph[2 * t + 1] = h2u(__floats2half2_rn(e2, e3));
            }
            #pragma unroll
            for (int cb = 0; cb < 4; ++cb) {
                uint32_t a = kb + aoff2 + (uint32_t)((kk * 16 * KSTR + cb * 16) * 2);
                uint32_t bh[4];
                ldsm_x4_trans(bh, a);
                mma16816(O[cb * 2],     Ph, bh);
                mma16816(O[cb * 2 + 1], Ph, bh + 2);
            }
        }
    }

    // ---- final l reduction (once, not per tile) ----
    l0 += __shfl_xor_sync(0xffffffffu, l0, 1);
    l0 += __shfl_xor_sync(0xffffffffu, l0, 2);
    l1 += __shfl_xor_sync(0xffffffffu, l1, 1);
    l1 += __shfl_xor_sync(0xffffffffu, l1, 2);

    // ---- epilogue: out = gamma * (O / l) + x ----
    const float inv0 = 1.0f / l0, inv1 = 1.0f / l1;
    const float gm = __ldg(gamma_p);
    const float* xb = x   + (size_t)b * NPOS * CH;
    float*       ob = out + (size_t)b * NPOS * CH;
    const int gr0 = i0 + wg * 16 + q4;
    const int gr1 = gr0 + 8;
    #pragma unroll
    for (int nb = 0; nb < 8; ++nb) {
        int c = nb * 8 + qm * 2;
        float2 xv0 = *(const float2*)(xb + (size_t)gr0 * CH + c);
        float2 xv1 = *(const float2*)(xb + (size_t)gr1 * CH + c);
        float2 o0, o1;
        o0.x = fmaf(gm, O[nb][0] * inv0, xv0.x);
        o0.y = fmaf(gm, O[nb][1] * inv0, xv0.y);
        o1.x = fmaf(gm, O[nb][2] * inv1, xv1.x);
        o1.y = fmaf(gm, O[nb][3] * inv1, xv1.y);
        *(float2*)(ob + (size_t)gr0 * CH + c) = o0;
        *(float2*)(ob + (size_t)gr1 * CH + c) = o1;
    }
}

// ---------------- launch ----------------
extern "C" void kernel_launch(void* const* d_in, const int* in_sizes, int n_in,
                              void* d_out, int out_size)
{
    const float* x     = (const float*)d_in[0];
    const float* gamma = (const float*)d_in[1];
    float* out         = (float*)d_out;

    cudaFuncSetAttribute(attn_kernel,
                         cudaFuncAttributeMaxDynamicSharedMemorySize, SMEM_TOTAL);

    convert_kernel<<<TOT_ELEMS / (256 * 4), 256>>>(x);
    attn_kernel<<<dim3(NPOS / (2 * BM), 2), 256, SMEM_TOTAL>>>(x, gamma, out);
}

// round 13
// speedup vs baseline: 1.1570x; 1.0269x over previous
#include <cuda_runtime.h>
#include <cuda_fp16.h>
#include <cstdint>

#define NPOS 8192
#define CH 64
#define BN 128         // keys per tile (two 64-key halves, one per warp of a pair)
#define NT (NPOS / BN) // 64
#define LOG2E 1.4426950408889634f

// ---------------- device scratch ----------------
#define TOT_ELEMS (2 * NPOS * CH)
__device__ __half g_hi[TOT_ELEMS];    // [b][n][c] fp16 hi
__device__ __half g_lo[TOT_ELEMS];    // [b][n][c] fp16 lo residual

// ---------------- helpers ----------------
__device__ __forceinline__ uint32_t smem_u32(const void* p) {
    uint32_t a;
    asm("{ .reg .u64 t; cvta.to.shared.u64 t, %1; cvt.u32.u64 %0, t; }" : "=r"(a) : "l"(p));
    return a;
}
__device__ __forceinline__ float ex2f(float v) {
    float r; asm("ex2.approx.ftz.f32 %0, %1;" : "=f"(r) : "f"(v)); return r;
}
__device__ __forceinline__ uint32_t h2u(__half2 h) { return *reinterpret_cast<uint32_t*>(&h); }

__device__ __forceinline__ void cp_async16(uint32_t dst, const void* src) {
    asm volatile("cp.async.cg.shared.global [%0], [%1], 16;" :: "r"(dst), "l"(src) : "memory");
}
__device__ __forceinline__ void cp_commit() {
    asm volatile("cp.async.commit_group;" ::: "memory");
}
template <int N>
__device__ __forceinline__ void cp_wait() {
    asm volatile("cp.async.wait_group %0;" :: "n"(N) : "memory");
}

__device__ __forceinline__ void ldsm_x4(uint32_t* r, uint32_t addr) {
    asm volatile("ldmatrix.sync.aligned.m8n8.x4.shared.b16 {%0,%1,%2,%3}, [%4];"
        : "=r"(r[0]), "=r"(r[1]), "=r"(r[2]), "=r"(r[3]) : "r"(addr));
}
__device__ __forceinline__ void ldsm_x4_trans(uint32_t* r, uint32_t addr) {
    asm volatile("ldmatrix.sync.aligned.m8n8.x4.trans.shared.b16 {%0,%1,%2,%3}, [%4];"
        : "=r"(r[0]), "=r"(r[1]), "=r"(r[2]), "=r"(r[3]) : "r"(addr));
}

// mma.sync m16n8k16 f16 -> f32 accumulate
__device__ __forceinline__ void mma16816(float* d, const uint32_t* a, const uint32_t* b) {
    asm volatile(
        "mma.sync.aligned.m16n8k16.row.col.f32.f16.f16.f32 "
        "{%0,%1,%2,%3}, {%4,%5,%6,%7}, {%8,%9}, {%0,%1,%2,%3};"
        : "+f"(d[0]), "+f"(d[1]), "+f"(d[2]), "+f"(d[3])
        : "r"(a[0]), "r"(a[1]), "r"(a[2]), "r"(a[3]), "r"(b[0]), "r"(b[1]));
}

// ---------------- smem layout ----------------
#define KSTR 72                         // row stride in halfs (64 + 8 pad)
#define KTILE (BN * KSTR * 2)           // one hi or lo tile = 18432 B
#define BUFSZ (2 * KTILE)               // hi + lo = 36864 B
#define SMEM_TOTAL (3 * BUFSZ)          // triple-buffered = 110592 B (1 CTA/SM)
// merge scratch (after the loop, K buffers are dead): 8 subtiles x 16 x 64 fp32 = 32 KB (+ m/l)
#define MG_O 0
#define MG_M (8 * 16 * 64 * 4)          // 32768
#define MG_L (MG_M + 8 * 16 * 4)        // 33280

// ---------------- pre-pass: fp32 -> fp16 hi/lo ----------------
__global__ __launch_bounds__(256) void convert_kernel(const float* __restrict__ x)
{
    size_t i4 = ((size_t)blockIdx.x * 256 + threadIdx.x) * 4;
    float4 v = *(const float4*)(x + i4);
    __half h0 = __float2half_rn(v.x), h1 = __float2half_rn(v.y);
    __half h2 = __float2half_rn(v.z), h3 = __float2half_rn(v.w);
    uint2 hw = make_uint2(h2u(__halves2half2(h0, h1)), h2u(__halves2half2(h2, h3)));
    *(uint2*)(g_hi + i4) = hw;
    __half l0 = __float2half_rn(v.x - __half2float(h0));
    __half l1 = __float2half_rn(v.y - __half2float(h1));
    __half l2 = __float2half_rn(v.z - __half2float(h2));
    __half l3 = __float2half_rn(v.w - __half2float(h3));
    uint2 lw = make_uint2(h2u(__halves2half2(l0, l1)), h2u(__halves2half2(l2, l3)));
    *(uint2*)(g_lo + i4) = lw;
}

// ---------------- main kernel: 16 warps, key-split pairs, end merge ----------------
__global__ __launch_bounds__(512, 1) void attn_kernel(
    const float* __restrict__ x,
    const float* __restrict__ gamma_p,
    float* __restrict__ out)
{
    extern __shared__ __align__(128) char smem[];
    const uint32_t sb = smem_u32(smem);
    const int tid  = threadIdx.x;
    const int w    = tid >> 5;
    const int lane = tid & 31;
    const int q4   = lane >> 2;
    const int qm   = lane & 3;
    const int sub  = w & 7;           // q-subtile (16 rows each)
    const int half = w >> 3;          // key half: 0 -> keys [0,64), 1 -> [64,128)
    const int b    = blockIdx.y;
    const int i0   = blockIdx.x * 128 + sub * 16;

    const __half* xhi = g_hi + (size_t)b * NPOS * CH;
    const __half* xlo = g_lo + (size_t)b * NPOS * CH;

    // ---- prefetch one shared K tile (hi+lo), all 512 threads ----
    auto prefetch = [&](int jt, int buf) {
        const uint32_t d = sb + (uint32_t)buf * BUFSZ;
        const int j0 = jt * BN;
        #pragma unroll
        for (int it = 0; it < 2; ++it) {           // 128 rows x 8 chunks of 16B
            int lin = it * 512 + tid;
            int row = lin >> 3, c16 = (lin & 7) * 8;
            uint32_t so = (uint32_t)(row * KSTR + c16) * 2;
            const size_t go = (size_t)(j0 + row) * CH + c16;
            cp_async16(d + so, xhi + go);
            cp_async16(d + KTILE + so, xlo + go);
        }
        cp_commit();
    };

    prefetch(0, 0);

    // ---- Q fragments (hi only) ----
    uint32_t Qh[4][4];
    {
        const int r0 = i0 + q4;
        #pragma unroll
        for (int kc = 0; kc < 4; ++kc) {
            int c = kc * 16 + qm * 2;
            Qh[kc][0] = *(const uint32_t*)(xhi + (size_t)r0 * CH + c);
            Qh[kc][1] = *(const uint32_t*)(xhi + (size_t)(r0 + 8) * CH + c);
            Qh[kc][2] = *(const uint32_t*)(xhi + (size_t)r0 * CH + c + 8);
            Qh[kc][3] = *(const uint32_t*)(xhi + (size_t)(r0 + 8) * CH + c + 8);
        }
    }

    // ldmatrix per-lane address offsets; each warp works in its 64-key half
    const uint32_t haloff = (uint32_t)(half * 64 * KSTR) * 2;
    const uint32_t aoff1 = haloff + (uint32_t)((((lane >> 4) & 1) * 8 + (lane & 7)) * KSTR
                                      + ((lane >> 3) & 1) * 8) * 2;
    const uint32_t aoff2 = haloff + (uint32_t)(((( lane >> 3) & 1) * 8 + (lane & 7)) * KSTR
                                      + ((lane >> 4) & 1) * 8) * 2;

    float m0 = -1e30f, m1 = -1e30f;
    float l0 = 0.0f, l1 = 0.0f;      // per-thread partials; reduced at the end
    float O[8][4];
    #pragma unroll
    for (int nb = 0; nb < 8; ++nb)
        #pragma unroll
        for (int e = 0; e < 4; ++e) O[nb][e] = 0.0f;

    for (int jt = 0; jt < NT; ++jt) {
        if (jt + 1 < NT) { prefetch(jt + 1, (jt + 1) % 3); cp_wait<1>(); }
        else             { cp_wait<0>(); }
        __syncthreads();

        const uint32_t kb = sb + (uint32_t)(jt % 3) * BUFSZ;

        // ---- GEMM1: S(16x64) = Qhi*Khi + Qhi*Klo  (this warp's key half) ----
        float S[8][4];
        #pragma unroll
        for (int nb = 0; nb < 8; ++nb)
            #pragma unroll
            for (int e = 0; e < 4; ++e) S[nb][e] = 0.0f;

        #pragma unroll
        for (int kc = 0; kc < 4; ++kc) {
            #pragma unroll
            for (int jb = 0; jb < 4; ++jb) {
                uint32_t a = kb + aoff1 + (uint32_t)((jb * 16 * KSTR + kc * 16) * 2);
                uint32_t bh[4], bl[4];
                ldsm_x4(bh, a);
                ldsm_x4(bl, a + KTILE);
                mma16816(S[jb * 2],     Qh[kc], bh);
                mma16816(S[jb * 2],     Qh[kc], bl);
                mma16816(S[jb * 2 + 1], Qh[kc], bh + 2);
                mma16816(S[jb * 2 + 1], Qh[kc], bl + 2);
            }
        }

        // ---- row max + rare O-rescale ----
        float mx0 = -1e30f, mx1 = -1e30f;
        #pragma unroll
        for (int nb = 0; nb < 8; ++nb) {
            mx0 = fmaxf(mx0, fmaxf(S[nb][0], S[nb][1]));
            mx1 = fmaxf(mx1, fmaxf(S[nb][2], S[nb][3]));
        }
        mx0 = fmaxf(mx0, __shfl_xor_sync(0xffffffffu, mx0, 1));
        mx0 = fmaxf(mx0, __shfl_xor_sync(0xffffffffu, mx0, 2));
        mx1 = fmaxf(mx1, __shfl_xor_sync(0xffffffffu, mx1, 1));
        mx1 = fmaxf(mx1, __shfl_xor_sync(0xffffffffu, mx1, 2));
        float mn0 = fmaxf(m0, mx0), mn1 = fmaxf(m1, mx1);

        if (mn0 > m0 || mn1 > m1) {
            float c0 = ex2f((m0 - mn0) * LOG2E), c1 = ex2f((m1 - mn1) * LOG2E);
            l0 *= c0; l1 *= c1;
            #pragma unroll
            for (int nb = 0; nb < 8; ++nb) {
                O[nb][0] *= c0; O[nb][1] *= c0; O[nb][2] *= c1; O[nb][3] *= c1;
            }
            m0 = mn0; m1 = mn1;
        }
        const float nmL0 = -m0 * LOG2E, nmL1 = -m1 * LOG2E;

        // ---- fused: exp/pack per 16-key block, then its GEMM2 MMAs ----
        #pragma unroll
        for (int kk = 0; kk < 4; ++kk) {
            uint32_t Ph[4];
            #pragma unroll
            for (int t = 0; t < 2; ++t) {
                int nb = 2 * kk + t;
                float e0 = ex2f(fmaf(S[nb][0], LOG2E, nmL0));
                float e1 = ex2f(fmaf(S[nb][1], LOG2E, nmL0));
                float e2 = ex2f(fmaf(S[nb][2], LOG2E, nmL1));
                float e3 = ex2f(fmaf(S[nb][3], LOG2E, nmL1));
                l0 += e0 + e1; l1 += e2 + e3;
                Ph[2 * t + 0] = h2u(__floats2half2_rn(e0, e1));
                Ph[2 * t + 1] = h2u(__floats2half2_rn(e2, e3));
            }
            #pragma unroll
            for (int cb = 0; cb < 4; ++cb) {
                uint32_t a = kb + aoff2 + (uint32_t)((kk * 16 * KSTR + cb * 16) * 2);
                uint32_t bh[4];
                ldsm_x4_trans(bh, a);
                mma16816(O[cb * 2],     Ph, bh);
                mma16816(O[cb * 2 + 1], Ph, bh + 2);
            }
        }
    }

    // ---- reduce l within quad (both halves) ----
    l0 += __shfl_xor_sync(0xffffffffu, l0, 1);
    l0 += __shfl_xor_sync(0xffffffffu, l0, 2);
    l1 += __shfl_xor_sync(0xffffffffu, l1, 1);
    l1 += __shfl_xor_sync(0xffffffffu, l1, 2);

    // ---- merge the two key-half partials (smem; K buffers are dead now) ----
    __syncthreads();
    float* smO = (float*)(smem + MG_O) + sub * 16 * 64;
    float* smM = (float*)(smem + MG_M) + sub * 16;
    float* smL = (float*)(smem + MG_L) + sub * 16;
    if (half == 1) {
        #pragma unroll
        for (int nb = 0; nb < 8; ++nb) {
            int c = nb * 8 + qm * 2;
            smO[q4 * 64 + c]       = O[nb][0];
            smO[q4 * 64 + c + 1]   = O[nb][1];
            smO[(q4 + 8) * 64 + c]     = O[nb][2];
            smO[(q4 + 8) * 64 + c + 1] = O[nb][3];
        }
        if (qm == 0) {
            smM[q4] = m0; smM[q4 + 8] = m1;
            smL[q4] = l0; smL[q4 + 8] = l1;
        }
    }
    __syncthreads();

    if (half == 0) {
        float mb0 = smM[q4], mb1 = smM[q4 + 8];
        float lb0 = smL[q4], lb1 = smL[q4 + 8];
        float M0 = fmaxf(m0, mb0), M1 = fmaxf(m1, mb1);
        float ca0 = ex2f((m0 - M0) * LOG2E), cb0 = ex2f((mb0 - M0) * LOG2E);
        float ca1 = ex2f((m1 - M1) * LOG2E), cb1 = ex2f((mb1 - M1) * LOG2E);
        float L0 = l0 * ca0 + lb0 * cb0;
        float L1 = l1 * ca1 + lb1 * cb1;

        const float inv0 = 1.0f / L0, inv1 = 1.0f / L1;
        const float gm = __ldg(gamma_p);
        const float* xb = x   + (size_t)b * NPOS * CH;
        float*       ob = out + (size_t)b * NPOS * CH;
        const int gr0 = i0 + q4;
        const int gr1 = gr0 + 8;
        #pragma unroll
        for (int nb = 0; nb < 8; ++nb) {
            int c = nb * 8 + qm * 2;
            float o00 = O[nb][0] * ca0 + smO[q4 * 64 + c]       * cb0;
            float o01 = O[nb][1] * ca0 + smO[q4 * 64 + c + 1]   * cb0;
            float o10 = O[nb][2] * ca1 + smO[(q4 + 8) * 64 + c]     * cb1;
            float o11 = O[nb][3] * ca1 + smO[(q4 + 8) * 64 + c + 1] * cb1;
            float2 xv0 = *(const float2*)(xb + (size_t)gr0 * CH + c);
            float2 xv1 = *(const float2*)(xb + (size_t)gr1 * CH + c);
            float2 r0, r1;
            r0.x = fmaf(gm, o00 * inv0, xv0.x);
            r0.y = fmaf(gm, o01 * inv0, xv0.y);
            r1.x = fmaf(gm, o10 * inv1, xv1.x);
            r1.y = fmaf(gm, o11 * inv1, xv1.y);
            *(float2*)(ob + (size_t)gr0 * CH + c) = r0;
            *(float2*)(ob + (size_t)gr1 * CH + c) = r1;
        }
    }
}

// ---------------- launch ----------------
extern "C" void kernel_launch(void* const* d_in, const int* in_sizes, int n_in,
                              void* d_out, int out_size)
{
    const float* x     = (const float*)d_in[0];
    const float* gamma = (const float*)d_in[1];
    float* out         = (float*)d_out;

    cudaFuncSetAttribute(attn_kernel,
                         cudaFuncAttributeMaxDynamicSharedMemorySize, SMEM_TOTAL);

    convert_kernel<<<TOT_ELEMS / (256 * 4), 256>>>(x);
    attn_kernel<<<dim3(NPOS / 128, 2), 512, SMEM_TOTAL>>>(x, gamma, out);
}